// round 6
// baseline (speedup 1.0000x reference)
#include <cuda_runtime.h>
#include <math.h>

#define T_ 2000
#define B_ 64
#define H_ 512
#define TB_ (T_*B_)

// ---- scratch ----
__device__ float g_wh[TB_*H_];
__device__ float g_wz[TB_*H_];
__device__ float g_h1[TB_*H_];
__device__ float g_hT2[16*4*512];     // [group][b][512 j]
__device__ float g_zhT2[16*4*512];    // [group][b][512 j]
__device__ unsigned int g_bar[16];

typedef unsigned long long ull;

#define FFMA2(acc, a, b) \
    asm("fma.rn.f32x2 %0, %1, %2, %0;" : "+l"(acc) : "l"(a), "l"(b))

__device__ __forceinline__ float f2lo(ull v){ return __uint_as_float((unsigned)v); }
__device__ __forceinline__ float f2hi(ull v){ return __uint_as_float((unsigned)(v>>32)); }

// =====================================================================
// Stage A: fused dual projection with f32x2 math.
// SIMD lanes = two adjacent n outputs. A duplicated (a,a) in SMEM.
// As3[k][(m&3)*32 + 2*(m>>2) + e]   (dup, bank-spread)
// Bh3[k][((n>>1)&1)*32 + 2*(n>>2) + (n&1)]
// =====================================================================
__global__ void __launch_bounds__(256) proj_kernel(
    const float* __restrict__ X,
    const float* __restrict__ Wh, const float* __restrict__ Wz,
    const float* __restrict__ bh, const float* __restrict__ bz,
    float* __restrict__ owh, float* __restrict__ owz)
{
    __shared__ float As3[32*128];
    __shared__ float Bh3[32*64];
    __shared__ float Bz3[32*64];

    const int tid = threadIdx.x;
    const int n0 = blockIdx.x * 64;
    const long m0 = (long)blockIdx.y * 64;
    const int pm = tid & 15;
    const int pn = tid >> 4;

    ull ah[4][2], az[4][2];
#pragma unroll
    for (int i = 0; i < 4; i++) { ah[i][0]=0ull; ah[i][1]=0ull; az[i][0]=0ull; az[i][1]=0ull; }

    for (int k0 = 0; k0 < 512; k0 += 32) {
        __syncthreads();
#pragma unroll
        for (int q = 0; q < 2; q++) {
            int c = tid + 256*q;
            int row = c >> 3;              // 0..63 (m or n)
            int col4 = (c & 7) * 4;        // k offset
            float4 xa = *(const float4*)&X[(m0 + row)*512 + k0 + col4];
            int mi = (row & 3)*32 + 2*(row >> 2);
            As3[(col4+0)*128 + mi] = xa.x; As3[(col4+0)*128 + mi+1] = xa.x;
            As3[(col4+1)*128 + mi] = xa.y; As3[(col4+1)*128 + mi+1] = xa.y;
            As3[(col4+2)*128 + mi] = xa.z; As3[(col4+2)*128 + mi+1] = xa.z;
            As3[(col4+3)*128 + mi] = xa.w; As3[(col4+3)*128 + mi+1] = xa.w;
            int ni = ((row >> 1)&1)*32 + 2*(row >> 2) + (row & 1);
            float4 wa = *(const float4*)&Wh[(long)(n0 + row)*512 + k0 + col4];
            Bh3[(col4+0)*64 + ni] = wa.x;
            Bh3[(col4+1)*64 + ni] = wa.y;
            Bh3[(col4+2)*64 + ni] = wa.z;
            Bh3[(col4+3)*64 + ni] = wa.w;
            float4 za = *(const float4*)&Wz[(long)(n0 + row)*512 + k0 + col4];
            Bz3[(col4+0)*64 + ni] = za.x;
            Bz3[(col4+1)*64 + ni] = za.y;
            Bz3[(col4+2)*64 + ni] = za.z;
            Bz3[(col4+3)*64 + ni] = za.w;
        }
        __syncthreads();
#pragma unroll
        for (int kk = 0; kk < 32; kk++) {
            const float* ap = &As3[kk*128 + 2*pm];
            ull a0 = *(const ull*)(ap);
            ull a1 = *(const ull*)(ap + 32);
            ull a2v = *(const ull*)(ap + 64);
            ull a3 = *(const ull*)(ap + 96);
            const float* bp = &Bh3[kk*64 + 2*pn];
            ull bh0 = *(const ull*)(bp);
            ull bh1 = *(const ull*)(bp + 32);
            const float* zp = &Bz3[kk*64 + 2*pn];
            ull bz0 = *(const ull*)(zp);
            ull bz1 = *(const ull*)(zp + 32);
            FFMA2(ah[0][0], a0, bh0); FFMA2(ah[0][1], a0, bh1);
            FFMA2(ah[1][0], a1, bh0); FFMA2(ah[1][1], a1, bh1);
            FFMA2(ah[2][0], a2v, bh0); FFMA2(ah[2][1], a2v, bh1);
            FFMA2(ah[3][0], a3, bh0); FFMA2(ah[3][1], a3, bh1);
            FFMA2(az[0][0], a0, bz0); FFMA2(az[0][1], a0, bz1);
            FFMA2(az[1][0], a1, bz0); FFMA2(az[1][1], a1, bz1);
            FFMA2(az[2][0], a2v, bz0); FFMA2(az[2][1], a2v, bz1);
            FFMA2(az[3][0], a3, bz0); FFMA2(az[3][1], a3, bz1);
        }
    }

    float bbh[4], bbz[4];
#pragma unroll
    for (int j = 0; j < 4; j++) { bbh[j] = bh[n0 + pn*4 + j]; bbz[j] = bz[n0 + pn*4 + j]; }
#pragma unroll
    for (int i = 0; i < 4; i++) {
        long r = (m0 + pm*4 + i)*512 + n0 + pn*4;
        float4 oh, oz;
        oh.x = f2lo(ah[i][0]) + bbh[0]; oh.y = f2hi(ah[i][0]) + bbh[1];
        oh.z = f2lo(ah[i][1]) + bbh[2]; oh.w = f2hi(ah[i][1]) + bbh[3];
        oz.x = f2lo(az[i][0]) + bbz[0]; oz.y = f2hi(az[i][0]) + bbz[1];
        oz.z = f2lo(az[i][1]) + bbz[2]; oz.w = f2hi(az[i][1]) + bbz[3];
        *(float4*)&owh[r] = oh;
        *(float4*)&owz[r] = oz;
    }
}

// =====================================================================
// Stage B: dual-group persistent scan with f32x2 GEMM.
// Grid: 128 CTAs = 8 pairs x 16 H-slices. Groups of 4 batches.
// hx layout [b][j] stride 516; U layout [i][j] stride 514.
// f32x2 accumulates even/odd-j partials; final lo+hi.
// =====================================================================
#define UST 514
#define HXT 516
// smem float offsets
#define OFF_UZ  0
#define OFF_UH  (32*UST)                 // 16448
#define OFF_HXA (2*32*UST)               // 32896
#define OFF_HXB (OFF_HXA + 4*HXT)        // +2064
#define OFF_RED (OFF_HXB + 4*HXT)
#define SCAN_SMEM_FLOATS (OFF_RED + 16*128)
#define SCAN_SMEM_BYTES  (SCAN_SMEM_FLOATS*4)

__device__ __forceinline__ void wait_flag(const unsigned int* f, unsigned tgt)
{
    unsigned v;
    do {
        asm volatile("ld.global.acquire.gpu.u32 %0, [%1];" : "=r"(v) : "l"(f));
    } while (v < tgt);
}

__device__ __forceinline__ void stage2(float* __restrict__ hx,
                                       const float* __restrict__ src,
                                       int warp, int lane)
{
    // warp w stages j in [w*64, w*64+64) for b = 0..3
#pragma unroll
    for (int r = 0; r < 2; r++) {
        int q = lane + 32*r;           // 0..63
        int b = q >> 4;                // 0..3
        int jo = (q & 15) * 4;         // 0..60
        float4 v = __ldcg((const float4*)(src + b*512 + warp*64 + jo));
        *(float4*)(hx + b*HXT + warp*64 + jo) = v;
    }
    __syncwarp();
}

__device__ __forceinline__ void gemm2(const float* __restrict__ hx,
                                      const float* __restrict__ Us,
                                      float* __restrict__ red, int tid)
{
    const int ks = tid >> 4;
    const int pos = tid & 15;
    const int pb = pos >> 3;
    const int pi = pos & 7;
    const int jb = ks * 32;

    ull acc[2][4];
#pragma unroll
    for (int b = 0; b < 2; b++)
#pragma unroll
        for (int q = 0; q < 4; q++) acc[b][q] = 0ull;

    const float* h0 = hx + (pb*2 + 0)*HXT + jb;
    const float* h1 = hx + (pb*2 + 1)*HXT + jb;
    const float* ub = Us + (pi*4)*UST + jb;
#pragma unroll
    for (int jj = 0; jj < 32; jj += 2) {
        ull hh0 = *(const ull*)(h0 + jj);
        ull hh1 = *(const ull*)(h1 + jj);
        ull u0 = *(const ull*)(ub + jj);
        ull u1 = *(const ull*)(ub + UST + jj);
        ull u2 = *(const ull*)(ub + 2*UST + jj);
        ull u3 = *(const ull*)(ub + 3*UST + jj);
        FFMA2(acc[0][0], hh0, u0); FFMA2(acc[0][1], hh0, u1);
        FFMA2(acc[0][2], hh0, u2); FFMA2(acc[0][3], hh0, u3);
        FFMA2(acc[1][0], hh1, u0); FFMA2(acc[1][1], hh1, u1);
        FFMA2(acc[1][2], hh1, u2); FFMA2(acc[1][3], hh1, u3);
    }
    float* rp = red + ks*128 + (pb*2)*32 + pi*4;
    float4 s0, s1;
    s0.x = f2lo(acc[0][0]) + f2hi(acc[0][0]);
    s0.y = f2lo(acc[0][1]) + f2hi(acc[0][1]);
    s0.z = f2lo(acc[0][2]) + f2hi(acc[0][2]);
    s0.w = f2lo(acc[0][3]) + f2hi(acc[0][3]);
    s1.x = f2lo(acc[1][0]) + f2hi(acc[1][0]);
    s1.y = f2lo(acc[1][1]) + f2hi(acc[1][1]);
    s1.z = f2lo(acc[1][2]) + f2hi(acc[1][2]);
    s1.w = f2lo(acc[1][3]) + f2hi(acc[1][3]);
    *(float4*)(rp)      = s0;
    *(float4*)(rp + 32) = s1;
}

__global__ void __launch_bounds__(256) scan2_kernel(
    const float* __restrict__ wh, const float* __restrict__ wz,
    const float* __restrict__ Uh, const float* __restrict__ Uz,
    float* __restrict__ out,
    float* __restrict__ hT2, float* __restrict__ zhT2,
    unsigned int* __restrict__ bar)
{
    extern __shared__ float sm[];
    float* Uzs = sm + OFF_UZ;
    float* Uhs = sm + OFF_UH;
    float* hxA = sm + OFF_HXA;
    float* hxB = sm + OFF_HXB;
    float* red = sm + OFF_RED;

    const int tid  = threadIdx.x;
    const int s    = blockIdx.x & 15;
    const int p    = blockIdx.x >> 4;
    const int i0   = s * 32;
    const int gA   = p;
    const int gB   = p + 8;
    const int warp = tid >> 5;
    const int lane = tid & 31;

    // one-time U slice load: [i][j], i-major, stride UST
    for (int idx = tid; idx < 32*512; idx += 256) {
        int i = idx >> 9;
        int j = idx & 511;
        Uzs[i*UST + j] = Uz[(i0 + i)*512 + j];
        Uhs[i*UST + j] = Uh[(i0 + i)*512 + j];
    }
    __syncthreads();

    // owner mapping (tid < 128): warp-contiguous stores
    const bool owner = tid < 128;
    const int bl = tid >> 5;           // 0..3 for owners
    const int il = tid & 31;
    const int jg = i0 + il;

    float* hTA  = hT2  + gA*2048;  float* hTB  = hT2  + gB*2048;
    float* zhTA = zhT2 + gA*2048;  float* zhTB = zhT2 + gB*2048;
    unsigned int* barA = bar + gA;
    unsigned int* barB = bar + gB;

    float hA = 0.f, hB = 0.f;

    for (int t = 0; t < T_; t++) {
        long baseA = ((long)(t*B_) + gA*4 + bl)*(long)H_ + jg;
        long baseB = ((long)(t*B_) + gB*4 + bl)*(long)H_ + jg;
        float wzA=0.f, whA=0.f, wzB=0.f, whB=0.f;
        if (owner) {
            wzA = __ldcg(wz + baseA); whA = __ldcg(wh + baseA);
            wzB = __ldcg(wz + baseB); whB = __ldcg(wh + baseB);
        }
        const unsigned tgtZ = 32u*(unsigned)t;
        const unsigned tgtH = tgtZ + 16u;

        // ---- stage h(t-1) for both groups (loads overlap waits) ----
        wait_flag(barA, tgtZ);
        stage2(hxA, hTA, warp, lane);
        wait_flag(barB, tgtZ);
        stage2(hxB, hTB, warp, lane);
        __syncthreads();

        // ================= Z_A =================
        gemm2(hxA, Uzs, red, tid);
        __syncthreads();
        float zA = 0.f, zhA = 0.f;
        if (owner) {
            float sum = 0.f;
#pragma unroll
            for (int k2 = 0; k2 < 16; k2++) sum += red[k2*128 + tid];
            zA  = __fdividef(1.f, 1.f + __expf(-(sum + wzA)));
            zhA = zA * hA;
            zhTA[bl*512 + jg] = zhA;
        }
        __syncthreads();
        if (tid == 0) { __threadfence(); atomicAdd(barA, 1u); }

        // ================= Z_B =================
        gemm2(hxB, Uzs, red, tid);
        __syncthreads();
        float zB = 0.f, zhB = 0.f;
        if (owner) {
            float sum = 0.f;
#pragma unroll
            for (int k2 = 0; k2 < 16; k2++) sum += red[k2*128 + tid];
            zB  = __fdividef(1.f, 1.f + __expf(-(sum + wzB)));
            zhB = zB * hB;
            zhTB[bl*512 + jg] = zhB;
        }
        __syncthreads();
        if (tid == 0) { __threadfence(); atomicAdd(barB, 1u); }

        // ---- stage z*h for both groups ----
        wait_flag(barA, tgtH);
        stage2(hxA, zhTA, warp, lane);
        wait_flag(barB, tgtH);
        stage2(hxB, zhTB, warp, lane);
        __syncthreads();

        // ================= H_A =================
        gemm2(hxA, Uhs, red, tid);
        __syncthreads();
        if (owner) {
            float sum = 0.f;
#pragma unroll
            for (int k2 = 0; k2 < 16; k2++) sum += red[k2*128 + tid];
            float ahv = sum + whA;
            float hc = __fdividef(2.f, 1.f + __expf(-2.f*ahv)) - 1.f;
            hA = zhA + (1.f - zA)*hc;
            hTA[bl*512 + jg] = hA;
            out[baseA] = hA;
        }
        __syncthreads();
        if (tid == 0) { __threadfence(); atomicAdd(barA, 1u); }

        // ================= H_B =================
        gemm2(hxB, Uhs, red, tid);
        __syncthreads();
        if (owner) {
            float sum = 0.f;
#pragma unroll
            for (int k2 = 0; k2 < 16; k2++) sum += red[k2*128 + tid];
            float ahv = sum + whB;
            float hc = __fdividef(2.f, 1.f + __expf(-2.f*ahv)) - 1.f;
            hB = zhB + (1.f - zB)*hc;
            hTB[bl*512 + jg] = hB;
            out[baseB] = hB;
        }
        __syncthreads();
        if (tid == 0) { __threadfence(); atomicAdd(barB, 1u); }
    }
}

// =====================================================================
extern "C" void kernel_launch(void* const* d_in, const int* in_sizes, int n_in,
                              void* d_out, int out_size)
{
    const float* x   = (const float*)d_in[0];
    const float* Wh0 = (const float*)d_in[1];
    const float* bh0 = (const float*)d_in[2];
    const float* Wz0 = (const float*)d_in[3];
    const float* bz0 = (const float*)d_in[4];
    const float* Uh0 = (const float*)d_in[5];
    const float* Uz0 = (const float*)d_in[6];
    const float* Wh1 = (const float*)d_in[7];
    const float* bh1 = (const float*)d_in[8];
    const float* Wz1 = (const float*)d_in[9];
    const float* bz1 = (const float*)d_in[10];
    const float* Uh1 = (const float*)d_in[11];
    const float* Uz1 = (const float*)d_in[12];
    float* out = (float*)d_out;

    float *p_wh, *p_wz, *p_h1, *p_hT2, *p_zhT2;
    unsigned int* p_bar;
    cudaGetSymbolAddress((void**)&p_wh, g_wh);
    cudaGetSymbolAddress((void**)&p_wz, g_wz);
    cudaGetSymbolAddress((void**)&p_h1, g_h1);
    cudaGetSymbolAddress((void**)&p_hT2, g_hT2);
    cudaGetSymbolAddress((void**)&p_zhT2, g_zhT2);
    cudaGetSymbolAddress((void**)&p_bar, g_bar);

    cudaFuncSetAttribute(scan2_kernel,
                         cudaFuncAttributeMaxDynamicSharedMemorySize, SCAN_SMEM_BYTES);

    dim3 pgrid(8, 2000);

    // ---- Layer 0 ----
    proj_kernel<<<pgrid, 256>>>(x, Wh0, Wz0, bh0, bz0, p_wh, p_wz);
    cudaMemsetAsync(p_hT2, 0, 16*4*512*sizeof(float));
    cudaMemsetAsync(p_bar, 0, 16*sizeof(unsigned int));
    scan2_kernel<<<128, 256, SCAN_SMEM_BYTES>>>(p_wh, p_wz, Uh0, Uz0,
                                                p_h1, p_hT2, p_zhT2, p_bar);

    // ---- Layer 1 ----
    proj_kernel<<<pgrid, 256>>>(p_h1, Wh1, Wz1, bh1, bz1, p_wh, p_wz);
    cudaMemsetAsync(p_hT2, 0, 16*4*512*sizeof(float));
    cudaMemsetAsync(p_bar, 0, 16*sizeof(unsigned int));
    scan2_kernel<<<128, 256, SCAN_SMEM_BYTES>>>(p_wh, p_wz, Uh1, Uz1,
                                                out, p_hT2, p_zhT2, p_bar);
}

// round 7
// speedup vs baseline: 1.4674x; 1.4674x over previous
#include <cuda_runtime.h>
#include <math.h>

#define T_ 2000
#define B_ 64
#define H_ 512
#define TB_ (T_*B_)

// ---- scratch ----
__device__ float g_wh[TB_*H_];
__device__ float g_wz[TB_*H_];
__device__ float g_h1[TB_*H_];
__device__ float g_hT2[16*512*4];     // [group][j][4b]
__device__ float g_zhT2[16*512*4];    // [group][j][4b]
__device__ unsigned int g_bar[16];

// =====================================================================
// tf32 helpers (3xTF32: x = hi + lo, compute hi*Whi + hi*Wlo + lo*Whi)
// =====================================================================
__device__ __forceinline__ unsigned cvt_tf32(float x) {
    unsigned r; asm("cvt.rna.tf32.f32 %0, %1;" : "=r"(r) : "f"(x)); return r;
}
__device__ __forceinline__ void split_tf32(float x, unsigned& hi, unsigned& lo) {
    hi = cvt_tf32(x);
    lo = cvt_tf32(x - __uint_as_float(hi));
}
__device__ __forceinline__ void mma_tf32(float* c, const unsigned* a, const unsigned* b) {
    asm volatile("mma.sync.aligned.m16n8k8.row.col.f32.tf32.tf32.f32 "
        "{%0,%1,%2,%3}, {%4,%5,%6,%7}, {%8,%9}, {%0,%1,%2,%3};"
        : "+f"(c[0]), "+f"(c[1]), "+f"(c[2]), "+f"(c[3])
        : "r"(a[0]), "r"(a[1]), "r"(a[2]), "r"(a[3]), "r"(b[0]), "r"(b[1]));
}

// =====================================================================
// Stage A: fused dual projection via 3xTF32 tensor cores.
// CTA tile 64M x 64N, k-chunks of 32. 8 warps = 4(M) x 2(N);
// each warp: m16 x n32 (4 n8-tiles). SMEM stride 36 => conflict-free
// fragment gathers (bank = 4*gid + tig, distinct across the warp).
// =====================================================================
#define XS 36

__global__ void __launch_bounds__(256) proj_kernel(
    const float* __restrict__ X,
    const float* __restrict__ Wh, const float* __restrict__ Wz,
    const float* __restrict__ bh, const float* __restrict__ bz,
    float* __restrict__ owh, float* __restrict__ owz)
{
    __shared__ float Xs[64*XS];
    __shared__ float Whs[64*XS];
    __shared__ float Wzs[64*XS];

    const int tid  = threadIdx.x;
    const int n0   = blockIdx.x * 64;
    const long m0  = (long)blockIdx.y * 64;
    const int lane = tid & 31;
    const int warp = tid >> 5;
    const int wm   = (warp & 3) * 16;   // warp m-offset in tile
    const int wn   = (warp >> 2) * 32;  // warp n-offset in tile
    const int gid  = lane >> 2;         // 0..7
    const int tig  = lane & 3;          // 0..3

    float ch[4][4], cz[4][4];
#pragma unroll
    for (int t = 0; t < 4; t++)
#pragma unroll
        for (int i = 0; i < 4; i++) { ch[t][i] = 0.f; cz[t][i] = 0.f; }

    for (int k0 = 0; k0 < 512; k0 += 32) {
        __syncthreads();
#pragma unroll
        for (int q = 0; q < 2; q++) {
            int idx = tid + 256*q;          // 0..511
            int row = idx >> 3;             // 0..63
            int col = (idx & 7) * 4;        // 0..28
            *(float4*)&Xs [row*XS + col] = *(const float4*)&X [(m0 + row)*512 + k0 + col];
            *(float4*)&Whs[row*XS + col] = *(const float4*)&Wh[(long)(n0 + row)*512 + k0 + col];
            *(float4*)&Wzs[row*XS + col] = *(const float4*)&Wz[(long)(n0 + row)*512 + k0 + col];
        }
        __syncthreads();

#pragma unroll
        for (int k8 = 0; k8 < 32; k8 += 8) {
            // ---- A fragment (X tile), hi/lo split ----
            unsigned ahi[4], alo[4];
            {
                float v0 = Xs[(wm + gid    )*XS + k8 + tig    ];
                float v1 = Xs[(wm + gid + 8)*XS + k8 + tig    ];
                float v2 = Xs[(wm + gid    )*XS + k8 + tig + 4];
                float v3 = Xs[(wm + gid + 8)*XS + k8 + tig + 4];
                split_tf32(v0, ahi[0], alo[0]);
                split_tf32(v1, ahi[1], alo[1]);
                split_tf32(v2, ahi[2], alo[2]);
                split_tf32(v3, ahi[3], alo[3]);
            }
#pragma unroll
            for (int t = 0; t < 4; t++) {
                const int nn = wn + t*8 + gid;   // row in W tile (= output col)
                unsigned bhh[2], bhl[2], bzh[2], bzl[2];
                {
                    float w0 = Whs[nn*XS + k8 + tig    ];
                    float w1 = Whs[nn*XS + k8 + tig + 4];
                    split_tf32(w0, bhh[0], bhl[0]);
                    split_tf32(w1, bhh[1], bhl[1]);
                    float z0 = Wzs[nn*XS + k8 + tig    ];
                    float z1 = Wzs[nn*XS + k8 + tig + 4];
                    split_tf32(z0, bzh[0], bzl[0]);
                    split_tf32(z1, bzh[1], bzl[1]);
                }
                mma_tf32(ch[t], ahi, bhh);
                mma_tf32(ch[t], ahi, bhl);
                mma_tf32(ch[t], alo, bhh);
                mma_tf32(cz[t], ahi, bzh);
                mma_tf32(cz[t], ahi, bzl);
                mma_tf32(cz[t], alo, bzh);
            }
        }
    }

    // ---- epilogue: add bias, store ----
#pragma unroll
    for (int t = 0; t < 4; t++) {
        int colg = n0 + wn + t*8 + tig*2;
        float bh0 = bh[colg], bh1 = bh[colg + 1];
        float bz0 = bz[colg], bz1 = bz[colg + 1];
        long r0 = (m0 + wm + gid    )*512 + colg;
        long r1 = (m0 + wm + gid + 8)*512 + colg;
        owh[r0]     = ch[t][0] + bh0;
        owh[r0 + 1] = ch[t][1] + bh1;
        owh[r1]     = ch[t][2] + bh0;
        owh[r1 + 1] = ch[t][3] + bh1;
        owz[r0]     = cz[t][0] + bz0;
        owz[r0 + 1] = cz[t][1] + bz1;
        owz[r1]     = cz[t][2] + bz0;
        owz[r1 + 1] = cz[t][3] + bz1;
    }
}

// =====================================================================
// Stage B: dual-group persistent GRU scan — round-5 version VERBATIM
// (best known: 36.07ms total). 128 CTAs = 8 pairs x 16 H-slices.
// =====================================================================
#define SCAN2_SMEM_FLOATS (16384*2 + 2048*2 + 2048)
#define SCAN2_SMEM_BYTES  (SCAN2_SMEM_FLOATS*4)

__device__ __forceinline__ void wait_flag(const unsigned int* f, unsigned tgt)
{
    unsigned v;
    do {
        asm volatile("ld.global.acquire.gpu.u32 %0, [%1];" : "=r"(v) : "l"(f));
    } while (v < tgt);
}

__device__ __forceinline__ void stage_group(float* __restrict__ hx,
                                            const float* __restrict__ src,
                                            int warp, int lane)
{
    const float4* s4 = (const float4*)(src + (warp << 8));
    float4* d4 = (float4*)(hx + (warp << 8));
    d4[lane]      = __ldcg(s4 + lane);
    d4[lane + 32] = __ldcg(s4 + lane + 32);
    __syncwarp();
}

__device__ __forceinline__ float gemm_phase(const float* __restrict__ hx,
                                            const float* __restrict__ Us,
                                            float* __restrict__ red, int tid)
{
    const int ks = tid >> 4;
    const int pos = tid & 15;
    const int pb = pos >> 3;
    const int pi = pos & 7;
    const int jbase = ks * 32;

    float a0x=0.f,a0y=0.f,a0z=0.f,a0w=0.f;
    float a1x=0.f,a1y=0.f,a1z=0.f,a1w=0.f;
    const float* hp = hx + jbase*4 + pb*2;
    const float* up = Us + jbase*32 + pi*4;
#pragma unroll
    for (int kk = 0; kk < 32; kk++) {
        float2 hv = *(const float2*)hp; hp += 4;
        float4 uv = *(const float4*)up; up += 32;
        a0x += hv.x*uv.x; a0y += hv.x*uv.y; a0z += hv.x*uv.z; a0w += hv.x*uv.w;
        a1x += hv.y*uv.x; a1y += hv.y*uv.y; a1z += hv.y*uv.z; a1w += hv.y*uv.w;
    }
    {
        float* rp = red + ks*128 + (pb*2)*32 + pi*4;
        *(float4*)(rp)      = make_float4(a0x,a0y,a0z,a0w);
        *(float4*)(rp + 32) = make_float4(a1x,a1y,a1z,a1w);
    }
    __syncthreads();

    float s = 0.f;
    if (tid < 128) {
        const int bl = tid & 3;
        const int il = tid >> 2;
#pragma unroll
        for (int k2 = 0; k2 < 16; k2++) s += red[k2*128 + bl*32 + il];
    }
    return s;
}

__global__ void __launch_bounds__(256) scan2_kernel(
    const float* __restrict__ wh, const float* __restrict__ wz,
    const float* __restrict__ Uh, const float* __restrict__ Uz,
    float* __restrict__ out,
    float* __restrict__ hT2, float* __restrict__ zhT2,
    unsigned int* __restrict__ bar)
{
    extern __shared__ float sm[];
    float* Uzs = sm;                   // 512*32
    float* Uhs = sm + 16384;           // 512*32
    float* hxA = sm + 32768;           // 512*4
    float* hxB = hxA + 2048;           // 512*4
    float* red = hxB + 2048;           // 16*128

    const int tid  = threadIdx.x;
    const int s    = blockIdx.x & 15;   // H slice
    const int p    = blockIdx.x >> 4;   // pair 0..7
    const int i0   = s * 32;
    const int gA   = p;
    const int gB   = p + 8;
    const int warp = tid >> 5;
    const int lane = tid & 31;

    for (int idx = tid; idx < 32*512; idx += 256) {
        int i = idx >> 9;
        int j = idx & 511;
        Uzs[j*32 + i] = Uz[(i0 + i)*512 + j];
        Uhs[j*32 + i] = Uh[(i0 + i)*512 + j];
    }
    __syncthreads();

    const int bl = tid & 3;
    const int il = tid >> 2;
    const int jg = i0 + il;
    const bool owner = tid < 128;
    const int xoff = jg*4 + bl;

    float* hTA  = hT2  + gA*2048;  float* hTB  = hT2  + gB*2048;
    float* zhTA = zhT2 + gA*2048;  float* zhTB = zhT2 + gB*2048;
    unsigned int* barA = bar + gA;
    unsigned int* barB = bar + gB;

    float hA = 0.f, hB = 0.f;

    for (int t = 0; t < T_; t++) {
        long baseA = ((long)(t*B_) + gA*4 + bl)*(long)H_ + jg;
        long baseB = ((long)(t*B_) + gB*4 + bl)*(long)H_ + jg;
        float wzA = 0.f, whA = 0.f, wzB = 0.f, whB = 0.f;
        if (owner) {
            wzA = __ldcg(wz + baseA); whA = __ldcg(wh + baseA);
            wzB = __ldcg(wz + baseB); whB = __ldcg(wh + baseB);
        }

        unsigned tgtZ = (unsigned)(2*t) * 16u;
        unsigned tgtH = (unsigned)(2*t + 1) * 16u;

        // ================= Z_A =================
        wait_flag(barA, tgtZ);
        stage_group(hxA, hTA, warp, lane);
        float sA = gemm_phase(hxA, Uzs, red, tid);
        float zA = 0.f, zhA = 0.f;
        if (owner) {
            zA  = __fdividef(1.f, 1.f + __expf(-(sA + wzA)));
            zhA = zA * hA;
            zhTA[xoff] = zhA;
        }
        __syncthreads();
        if (tid == 0) { __threadfence(); atomicAdd(barA, 1u); }

        // ================= Z_B =================
        wait_flag(barB, tgtZ);
        stage_group(hxB, hTB, warp, lane);
        float sB = gemm_phase(hxB, Uzs, red, tid);
        float zB = 0.f, zhB = 0.f;
        if (owner) {
            zB  = __fdividef(1.f, 1.f + __expf(-(sB + wzB)));
            zhB = zB * hB;
            zhTB[xoff] = zhB;
        }
        __syncthreads();
        if (tid == 0) { __threadfence(); atomicAdd(barB, 1u); }

        // ================= H_A =================
        wait_flag(barA, tgtH);
        stage_group(hxA, zhTA, warp, lane);
        float s2A = gemm_phase(hxA, Uhs, red, tid);
        if (owner) {
            float ahv = s2A + whA;
            float hc = __fdividef(2.f, 1.f + __expf(-2.f*ahv)) - 1.f;
            hA = zhA + (1.f - zA)*hc;
            hTA[xoff] = hA;
            out[baseA] = hA;
        }
        __syncthreads();
        if (tid == 0) { __threadfence(); atomicAdd(barA, 1u); }

        // ================= H_B =================
        wait_flag(barB, tgtH);
        stage_group(hxB, zhTB, warp, lane);
        float s2B = gemm_phase(hxB, Uhs, red, tid);
        if (owner) {
            float ahv = s2B + whB;
            float hc = __fdividef(2.f, 1.f + __expf(-2.f*ahv)) - 1.f;
            hB = zhB + (1.f - zB)*hc;
            hTB[xoff] = hB;
            out[baseB] = hB;
        }
        __syncthreads();
        if (tid == 0) { __threadfence(); atomicAdd(barB, 1u); }
    }
}

// =====================================================================
extern "C" void kernel_launch(void* const* d_in, const int* in_sizes, int n_in,
                              void* d_out, int out_size)
{
    const float* x   = (const float*)d_in[0];
    const float* Wh0 = (const float*)d_in[1];
    const float* bh0 = (const float*)d_in[2];
    const float* Wz0 = (const float*)d_in[3];
    const float* bz0 = (const float*)d_in[4];
    const float* Uh0 = (const float*)d_in[5];
    const float* Uz0 = (const float*)d_in[6];
    const float* Wh1 = (const float*)d_in[7];
    const float* bh1 = (const float*)d_in[8];
    const float* Wz1 = (const float*)d_in[9];
    const float* bz1 = (const float*)d_in[10];
    const float* Uh1 = (const float*)d_in[11];
    const float* Uz1 = (const float*)d_in[12];
    float* out = (float*)d_out;

    float *p_wh, *p_wz, *p_h1, *p_hT2, *p_zhT2;
    unsigned int* p_bar;
    cudaGetSymbolAddress((void**)&p_wh, g_wh);
    cudaGetSymbolAddress((void**)&p_wz, g_wz);
    cudaGetSymbolAddress((void**)&p_h1, g_h1);
    cudaGetSymbolAddress((void**)&p_hT2, g_hT2);
    cudaGetSymbolAddress((void**)&p_zhT2, g_zhT2);
    cudaGetSymbolAddress((void**)&p_bar, g_bar);

    cudaFuncSetAttribute(scan2_kernel,
                         cudaFuncAttributeMaxDynamicSharedMemorySize, SCAN2_SMEM_BYTES);

    dim3 pgrid(8, 2000);

    // ---- Layer 0 ----
    proj_kernel<<<pgrid, 256>>>(x, Wh0, Wz0, bh0, bz0, p_wh, p_wz);
    cudaMemsetAsync(p_hT2, 0, 16*512*4*sizeof(float));
    cudaMemsetAsync(p_bar, 0, 16*sizeof(unsigned int));
    scan2_kernel<<<128, 256, SCAN2_SMEM_BYTES>>>(p_wh, p_wz, Uh0, Uz0,
                                                 p_h1, p_hT2, p_zhT2, p_bar);

    // ---- Layer 1 ----
    proj_kernel<<<pgrid, 256>>>(p_h1, Wh1, Wz1, bh1, bz1, p_wh, p_wz);
    cudaMemsetAsync(p_hT2, 0, 16*512*4*sizeof(float));
    cudaMemsetAsync(p_bar, 0, 16*sizeof(unsigned int));
    scan2_kernel<<<128, 256, SCAN2_SMEM_BYTES>>>(p_wh, p_wz, Uh1, Uz1,
                                                 out, p_hT2, p_zhT2, p_bar);
}

// round 8
// speedup vs baseline: 1.4785x; 1.0076x over previous
#include <cuda_runtime.h>
#include <math.h>

#define T_ 2000
#define B_ 64
#define H_ 512
#define TB_ (T_*B_)

// ---- scratch ----
__device__ float g_wh[TB_*H_];
__device__ float g_wz[TB_*H_];
__device__ float g_h1[TB_*H_];
__device__ float g_hT2[16*4*512];     // [group][b][512 j]
__device__ float g_zhT2[16*4*512];    // [group][b][512 j]
__device__ unsigned int g_bar[16];

// =====================================================================
// tf32 helpers (proj, 3xTF32 — unchanged from round 7, proven)
// =====================================================================
__device__ __forceinline__ unsigned cvt_tf32(float x) {
    unsigned r; asm("cvt.rna.tf32.f32 %0, %1;" : "=r"(r) : "f"(x)); return r;
}
__device__ __forceinline__ void split_tf32(float x, unsigned& hi, unsigned& lo) {
    hi = cvt_tf32(x);
    lo = cvt_tf32(x - __uint_as_float(hi));
}
__device__ __forceinline__ void mma_tf32(float* c, const unsigned* a, const unsigned* b) {
    asm volatile("mma.sync.aligned.m16n8k8.row.col.f32.tf32.tf32.f32 "
        "{%0,%1,%2,%3}, {%4,%5,%6,%7}, {%8,%9}, {%0,%1,%2,%3};"
        : "+f"(c[0]), "+f"(c[1]), "+f"(c[2]), "+f"(c[3])
        : "r"(a[0]), "r"(a[1]), "r"(a[2]), "r"(a[3]), "r"(b[0]), "r"(b[1]));
}

#define XS 36

__global__ void __launch_bounds__(256) proj_kernel(
    const float* __restrict__ X,
    const float* __restrict__ Wh, const float* __restrict__ Wz,
    const float* __restrict__ bh, const float* __restrict__ bz,
    float* __restrict__ owh, float* __restrict__ owz)
{
    __shared__ float Xs[64*XS];
    __shared__ float Whs[64*XS];
    __shared__ float Wzs[64*XS];

    const int tid  = threadIdx.x;
    const int n0   = blockIdx.x * 64;
    const long m0  = (long)blockIdx.y * 64;
    const int lane = tid & 31;
    const int warp = tid >> 5;
    const int wm   = (warp & 3) * 16;
    const int wn   = (warp >> 2) * 32;
    const int gid  = lane >> 2;
    const int tig  = lane & 3;

    float ch[4][4], cz[4][4];
#pragma unroll
    for (int t = 0; t < 4; t++)
#pragma unroll
        for (int i = 0; i < 4; i++) { ch[t][i] = 0.f; cz[t][i] = 0.f; }

    for (int k0 = 0; k0 < 512; k0 += 32) {
        __syncthreads();
#pragma unroll
        for (int q = 0; q < 2; q++) {
            int idx = tid + 256*q;
            int row = idx >> 3;
            int col = (idx & 7) * 4;
            *(float4*)&Xs [row*XS + col] = *(const float4*)&X [(m0 + row)*512 + k0 + col];
            *(float4*)&Whs[row*XS + col] = *(const float4*)&Wh[(long)(n0 + row)*512 + k0 + col];
            *(float4*)&Wzs[row*XS + col] = *(const float4*)&Wz[(long)(n0 + row)*512 + k0 + col];
        }
        __syncthreads();

#pragma unroll
        for (int k8 = 0; k8 < 32; k8 += 8) {
            unsigned ahi[4], alo[4];
            {
                float v0 = Xs[(wm + gid    )*XS + k8 + tig    ];
                float v1 = Xs[(wm + gid + 8)*XS + k8 + tig    ];
                float v2 = Xs[(wm + gid    )*XS + k8 + tig + 4];
                float v3 = Xs[(wm + gid + 8)*XS + k8 + tig + 4];
                split_tf32(v0, ahi[0], alo[0]);
                split_tf32(v1, ahi[1], alo[1]);
                split_tf32(v2, ahi[2], alo[2]);
                split_tf32(v3, ahi[3], alo[3]);
            }
#pragma unroll
            for (int t = 0; t < 4; t++) {
                const int nn = wn + t*8 + gid;
                unsigned bhh[2], bhl[2], bzh[2], bzl[2];
                {
                    float w0 = Whs[nn*XS + k8 + tig    ];
                    float w1 = Whs[nn*XS + k8 + tig + 4];
                    split_tf32(w0, bhh[0], bhl[0]);
                    split_tf32(w1, bhh[1], bhl[1]);
                    float z0 = Wzs[nn*XS + k8 + tig    ];
                    float z1 = Wzs[nn*XS + k8 + tig + 4];
                    split_tf32(z0, bzh[0], bzl[0]);
                    split_tf32(z1, bzh[1], bzl[1]);
                }
                mma_tf32(ch[t], ahi, bhh);
                mma_tf32(ch[t], ahi, bhl);
                mma_tf32(ch[t], alo, bhh);
                mma_tf32(cz[t], ahi, bzh);
                mma_tf32(cz[t], ahi, bzl);
                mma_tf32(cz[t], alo, bzh);
            }
        }
    }

#pragma unroll
    for (int t = 0; t < 4; t++) {
        int colg = n0 + wn + t*8 + tig*2;
        float bh0 = bh[colg], bh1 = bh[colg + 1];
        float bz0 = bz[colg], bz1 = bz[colg + 1];
        long r0 = (m0 + wm + gid    )*512 + colg;
        long r1 = (m0 + wm + gid + 8)*512 + colg;
        owh[r0]     = ch[t][0] + bh0;
        owh[r0 + 1] = ch[t][1] + bh1;
        owh[r1]     = ch[t][2] + bh0;
        owh[r1 + 1] = ch[t][3] + bh1;
        owz[r0]     = cz[t][0] + bz0;
        owz[r0 + 1] = cz[t][1] + bz1;
        owz[r1]     = cz[t][2] + bz0;
        owz[r1 + 1] = cz[t][3] + bz1;
    }
}

// =====================================================================
// bf16 split helpers (scan)
// word packs (even j -> low 16, odd j -> high 16)
// =====================================================================
__device__ __forceinline__ unsigned pack_bf16(float lo_elem, float hi_elem) {
    unsigned w;
    asm("cvt.rn.bf16x2.f32 %0, %1, %2;" : "=r"(w) : "f"(hi_elem), "f"(lo_elem));
    return w;
}
__device__ __forceinline__ float bfw_lo(unsigned w) { return __uint_as_float(w << 16); }
__device__ __forceinline__ float bfw_hi(unsigned w) { return __uint_as_float(w & 0xFFFF0000u); }

__device__ __forceinline__ void mma_bf16(float* c, const unsigned* a, const unsigned* b) {
    asm volatile("mma.sync.aligned.m16n8k16.row.col.f32.bf16.bf16.f32 "
        "{%0,%1,%2,%3}, {%4,%5,%6,%7}, {%8,%9}, {%0,%1,%2,%3};"
        : "+f"(c[0]), "+f"(c[1]), "+f"(c[2]), "+f"(c[3])
        : "r"(a[0]), "r"(a[1]), "r"(a[2]), "r"(a[3]), "r"(b[0]), "r"(b[1]));
}

// =====================================================================
// Stage B: dual-group persistent scan with split-bf16 tensor-core GEMM.
// Grid: 128 CTAs = 8 pairs x 16 H-slices; groups of 4 batches.
// U pre-split once into packed bf16 hi/lo planes (stride 260 words ->
// conflict-free fragment gathers). h split per phase during staging.
// 3-term MMA: Uhi*hhi + Uhi*hlo + Ulo*hhi, fp32 accumulate.
// =====================================================================
#define UPS 260                      // words per row (256 + pad)
#define UPLANE (32*UPS)              // 8320 words per U plane
#define BPLANE (8*UPS)               // 2080 words per h plane
#define OFF_UZH 0
#define OFF_UZL (OFF_UZH + UPLANE)
#define OFF_UHH (OFF_UZL + UPLANE)
#define OFF_UHL (OFF_UHH + UPLANE)
#define OFF_BAH (OFF_UHL + UPLANE)   // group A hi
#define OFF_BAL (OFF_BAH + BPLANE)
#define OFF_BBH (OFF_BAL + BPLANE)
#define OFF_BBL (OFF_BBH + BPLANE)
#define OFF_RED (OFF_BBL + BPLANE)   // 8 warps x 264
#define SCAN_SMEM_WORDS (OFF_RED + 8*264)
#define SCAN_SMEM_BYTES (SCAN_SMEM_WORDS*4)

__device__ __forceinline__ void wait_flag(const unsigned int* f, unsigned tgt)
{
    unsigned v;
    do {
        asm volatile("ld.global.acquire.gpu.u32 %0, [%1];" : "=r"(v) : "l"(f));
    } while (v < tgt);
}

// stage group h -> packed bf16 hi/lo planes [n][k2], warp-local k range
__device__ __forceinline__ void stage_bf16(unsigned* __restrict__ Bh,
                                           unsigned* __restrict__ Bl,
                                           const float* __restrict__ src,
                                           int warp, int lane)
{
#pragma unroll
    for (int r = 0; r < 2; r++) {
        int q = lane + 32*r;            // 0..63
        int b = q >> 4;                 // 0..3
        int quad = q & 15;              // j quad
        float4 v = __ldcg((const float4*)(src + b*512 + (warp << 6) + quad*4));
        unsigned h0 = pack_bf16(v.x, v.y);
        unsigned h1 = pack_bf16(v.z, v.w);
        unsigned l0 = pack_bf16(v.x - bfw_lo(h0), v.y - bfw_hi(h0));
        unsigned l1 = pack_bf16(v.z - bfw_lo(h1), v.w - bfw_hi(h1));
        int k2 = (warp << 5) + quad*2;
        *(uint2*)(Bh + b*UPS + k2) = make_uint2(h0, h1);
        *(uint2*)(Bl + b*UPS + k2) = make_uint2(l0, l1);
    }
    __syncwarp();
}

// warp-level GEMM partial: C[32i x 8n] over warp's k64 range; red write.
__device__ __forceinline__ void gemm_mma(const unsigned* __restrict__ Bh,
                                         const unsigned* __restrict__ Bl,
                                         const unsigned* __restrict__ Uh,
                                         const unsigned* __restrict__ Ul,
                                         float* __restrict__ red,
                                         int warp, int lane)
{
    const int gid = lane >> 2;
    const int tig = lane & 3;

    float c0[4] = {0.f,0.f,0.f,0.f};   // m-tile 0 (i 0..15)
    float c1[4] = {0.f,0.f,0.f,0.f};   // m-tile 1 (i 16..31)

#pragma unroll
    for (int kc = 0; kc < 4; kc++) {
        const int k2 = (warp << 5) + (kc << 3) + tig;
        unsigned bh[2], bl[2];
        bh[0] = Bh[gid*UPS + k2];  bh[1] = Bh[gid*UPS + k2 + 4];
        bl[0] = Bl[gid*UPS + k2];  bl[1] = Bl[gid*UPS + k2 + 4];

#pragma unroll
        for (int iw = 0; iw < 2; iw++) {
            const int r0 = iw*16 + gid;
            unsigned ah[4], al[4];
            ah[0] = Uh[(r0    )*UPS + k2    ];
            ah[1] = Uh[(r0 + 8)*UPS + k2    ];
            ah[2] = Uh[(r0    )*UPS + k2 + 4];
            ah[3] = Uh[(r0 + 8)*UPS + k2 + 4];
            al[0] = Ul[(r0    )*UPS + k2    ];
            al[1] = Ul[(r0 + 8)*UPS + k2    ];
            al[2] = Ul[(r0    )*UPS + k2 + 4];
            al[3] = Ul[(r0 + 8)*UPS + k2 + 4];
            float* cc = iw ? c1 : c0;
            mma_bf16(cc, ah, bh);
            mma_bf16(cc, ah, bl);
            mma_bf16(cc, al, bh);
        }
    }

    // red[w*264 + n*33 + i]
    float* rp = red + warp*264;
#pragma unroll
    for (int iw = 0; iw < 2; iw++) {
        const float* cc = iw ? c1 : c0;
        int ia = iw*16 + gid;
        rp[(2*tig    )*33 + ia    ] = cc[0];
        rp[(2*tig + 1)*33 + ia    ] = cc[1];
        rp[(2*tig    )*33 + ia + 8] = cc[2];
        rp[(2*tig + 1)*33 + ia + 8] = cc[3];
    }
}

__global__ void __launch_bounds__(256) scan2_kernel(
    const float* __restrict__ wh, const float* __restrict__ wz,
    const float* __restrict__ Uh, const float* __restrict__ Uz,
    float* __restrict__ out,
    float* __restrict__ hT2, float* __restrict__ zhT2,
    unsigned int* __restrict__ bar)
{
    extern __shared__ float sm[];
    unsigned* UZH = (unsigned*)(sm + OFF_UZH);
    unsigned* UZL = (unsigned*)(sm + OFF_UZL);
    unsigned* UHH = (unsigned*)(sm + OFF_UHH);
    unsigned* UHL = (unsigned*)(sm + OFF_UHL);
    unsigned* BAH = (unsigned*)(sm + OFF_BAH);
    unsigned* BAL = (unsigned*)(sm + OFF_BAL);
    unsigned* BBH = (unsigned*)(sm + OFF_BBH);
    unsigned* BBL = (unsigned*)(sm + OFF_BBL);
    float*    red = sm + OFF_RED;

    const int tid  = threadIdx.x;
    const int s    = blockIdx.x & 15;
    const int p    = blockIdx.x >> 4;
    const int i0   = s * 32;
    const int gA   = p;
    const int gB   = p + 8;
    const int warp = tid >> 5;
    const int lane = tid & 31;

    // one-time U pre-split into packed bf16 hi/lo planes
    for (int idx = tid; idx < 32*256; idx += 256) {
        int i  = idx >> 8;
        int j2 = idx & 255;
        float2 uz = *(const float2*)&Uz[(i0 + i)*512 + 2*j2];
        unsigned h = pack_bf16(uz.x, uz.y);
        UZH[i*UPS + j2] = h;
        UZL[i*UPS + j2] = pack_bf16(uz.x - bfw_lo(h), uz.y - bfw_hi(h));
        float2 uh = *(const float2*)&Uh[(i0 + i)*512 + 2*j2];
        unsigned h2 = pack_bf16(uh.x, uh.y);
        UHH[i*UPS + j2] = h2;
        UHL[i*UPS + j2] = pack_bf16(uh.x - bfw_lo(h2), uh.y - bfw_hi(h2));
    }
    __syncthreads();

    // owner mapping (tid < 128): bl = tid>>5 (0..3), il = tid&31
    const bool owner = tid < 128;
    const int bl = tid >> 5;
    const int il = tid & 31;
    const int jg = i0 + il;

    float* hTA  = hT2  + gA*2048;  float* hTB  = hT2  + gB*2048;
    float* zhTA = zhT2 + gA*2048;  float* zhTB = zhT2 + gB*2048;
    unsigned int* barA = bar + gA;
    unsigned int* barB = bar + gB;

    float hA = 0.f, hB = 0.f;

    for (int t = 0; t < T_; t++) {
        long baseA = ((long)(t*B_) + gA*4 + bl)*(long)H_ + jg;
        long baseB = ((long)(t*B_) + gB*4 + bl)*(long)H_ + jg;
        float wzA = 0.f, whA = 0.f, wzB = 0.f, whB = 0.f;
        if (owner) {
            wzA = __ldcg(wz + baseA); whA = __ldcg(wh + baseA);
            wzB = __ldcg(wz + baseB); whB = __ldcg(wh + baseB);
        }

        unsigned tgtZ = (unsigned)(2*t) * 16u;
        unsigned tgtH = (unsigned)(2*t + 1) * 16u;

        // ================= Z_A =================
        wait_flag(barA, tgtZ);
        stage_bf16(BAH, BAL, hTA, warp, lane);
        gemm_mma(BAH, BAL, UZH, UZL, red, warp, lane);
        __syncthreads();
        float zA = 0.f, zhA = 0.f;
        if (owner) {
            float sum = 0.f;
#pragma unroll
            for (int w = 0; w < 8; w++) sum += red[w*264 + bl*33 + il];
            zA  = __fdividef(1.f, 1.f + __expf(-(sum + wzA)));
            zhA = zA * hA;
            zhTA[bl*512 + jg] = zhA;
        }
        __syncthreads();
        if (tid == 0) { __threadfence(); atomicAdd(barA, 1u); }

        // ================= Z_B =================
        wait_flag(barB, tgtZ);
        stage_bf16(BBH, BBL, hTB, warp, lane);
        gemm_mma(BBH, BBL, UZH, UZL, red, warp, lane);
        __syncthreads();
        float zB = 0.f, zhB = 0.f;
        if (owner) {
            float sum = 0.f;
#pragma unroll
            for (int w = 0; w < 8; w++) sum += red[w*264 + bl*33 + il];
            zB  = __fdividef(1.f, 1.f + __expf(-(sum + wzB)));
            zhB = zB * hB;
            zhTB[bl*512 + jg] = zhB;
        }
        __syncthreads();
        if (tid == 0) { __threadfence(); atomicAdd(barB, 1u); }

        // ================= H_A =================
        wait_flag(barA, tgtH);
        stage_bf16(BAH, BAL, zhTA, warp, lane);
        gemm_mma(BAH, BAL, UHH, UHL, red, warp, lane);
        __syncthreads();
        if (owner) {
            float sum = 0.f;
#pragma unroll
            for (int w = 0; w < 8; w++) sum += red[w*264 + bl*33 + il];
            float ahv = sum + whA;
            float hc = __fdividef(2.f, 1.f + __expf(-2.f*ahv)) - 1.f;
            hA = zhA + (1.f - zA)*hc;
            hTA[bl*512 + jg] = hA;
            out[baseA] = hA;
        }
        __syncthreads();
        if (tid == 0) { __threadfence(); atomicAdd(barA, 1u); }

        // ================= H_B =================
        wait_flag(barB, tgtH);
        stage_bf16(BBH, BBL, zhTB, warp, lane);
        gemm_mma(BBH, BBL, UHH, UHL, red, warp, lane);
        __syncthreads();
        if (owner) {
            float sum = 0.f;
#pragma unroll
            for (int w = 0; w < 8; w++) sum += red[w*264 + bl*33 + il];
            float ahv = sum + whB;
            float hc = __fdividef(2.f, 1.f + __expf(-2.f*ahv)) - 1.f;
            hB = zhB + (1.f - zB)*hc;
            hTB[bl*512 + jg] = hB;
            out[baseB] = hB;
        }
        __syncthreads();
        if (tid == 0) { __threadfence(); atomicAdd(barB, 1u); }
    }
}

// =====================================================================
extern "C" void kernel_launch(void* const* d_in, const int* in_sizes, int n_in,
                              void* d_out, int out_size)
{
    const float* x   = (const float*)d_in[0];
    const float* Wh0 = (const float*)d_in[1];
    const float* bh0 = (const float*)d_in[2];
    const float* Wz0 = (const float*)d_in[3];
    const float* bz0 = (const float*)d_in[4];
    const float* Uh0 = (const float*)d_in[5];
    const float* Uz0 = (const float*)d_in[6];
    const float* Wh1 = (const float*)d_in[7];
    const float* bh1 = (const float*)d_in[8];
    const float* Wz1 = (const float*)d_in[9];
    const float* bz1 = (const float*)d_in[10];
    const float* Uh1 = (const float*)d_in[11];
    const float* Uz1 = (const float*)d_in[12];
    float* out = (float*)d_out;

    float *p_wh, *p_wz, *p_h1, *p_hT2, *p_zhT2;
    unsigned int* p_bar;
    cudaGetSymbolAddress((void**)&p_wh, g_wh);
    cudaGetSymbolAddress((void**)&p_wz, g_wz);
    cudaGetSymbolAddress((void**)&p_h1, g_h1);
    cudaGetSymbolAddress((void**)&p_hT2, g_hT2);
    cudaGetSymbolAddress((void**)&p_zhT2, g_zhT2);
    cudaGetSymbolAddress((void**)&p_bar, g_bar);

    cudaFuncSetAttribute(scan2_kernel,
                         cudaFuncAttributeMaxDynamicSharedMemorySize, SCAN_SMEM_BYTES);

    dim3 pgrid(8, 2000);

    // ---- Layer 0 ----
    proj_kernel<<<pgrid, 256>>>(x, Wh0, Wz0, bh0, bz0, p_wh, p_wz);
    cudaMemsetAsync(p_hT2, 0, 16*4*512*sizeof(float));
    cudaMemsetAsync(p_bar, 0, 16*sizeof(unsigned int));
    scan2_kernel<<<128, 256, SCAN_SMEM_BYTES>>>(p_wh, p_wz, Uh0, Uz0,
                                                p_h1, p_hT2, p_zhT2, p_bar);

    // ---- Layer 1 ----
    proj_kernel<<<pgrid, 256>>>(p_h1, Wh1, Wz1, bh1, bz1, p_wh, p_wz);
    cudaMemsetAsync(p_hT2, 0, 16*4*512*sizeof(float));
    cudaMemsetAsync(p_bar, 0, 16*sizeof(unsigned int));
    scan2_kernel<<<128, 256, SCAN_SMEM_BYTES>>>(p_wh, p_wz, Uh1, Uz1,
                                                out, p_hT2, p_zhT2, p_bar);
}

// round 10
// speedup vs baseline: 2.0606x; 1.3937x over previous
#include <cuda_runtime.h>
#include <math.h>

#define T_ 2000
#define B_ 64
#define H_ 512
#define TB_ (T_*B_)

// ---- scratch ----
__device__ float g_wh[TB_*H_];
__device__ float g_wz[TB_*H_];
__device__ float g_h1[TB_*H_];
__device__ float g_hT[8*8*512];      // [group][b][512 j]
__device__ float g_zhT[8*8*512];     // [group][b][512 j]
__device__ unsigned int g_bar[8];

// =====================================================================
// tf32 helpers (proj, 3xTF32 — round-8 proven version, VERBATIM)
// =====================================================================
__device__ __forceinline__ unsigned cvt_tf32(float x) {
    unsigned r; asm("cvt.rna.tf32.f32 %0, %1;" : "=r"(r) : "f"(x)); return r;
}
__device__ __forceinline__ void split_tf32(float x, unsigned& hi, unsigned& lo) {
    hi = cvt_tf32(x);
    lo = cvt_tf32(x - __uint_as_float(hi));
}
__device__ __forceinline__ void mma_tf32(float* c, const unsigned* a, const unsigned* b) {
    asm volatile("mma.sync.aligned.m16n8k8.row.col.f32.tf32.tf32.f32 "
        "{%0,%1,%2,%3}, {%4,%5,%6,%7}, {%8,%9}, {%0,%1,%2,%3};"
        : "+f"(c[0]), "+f"(c[1]), "+f"(c[2]), "+f"(c[3])
        : "r"(a[0]), "r"(a[1]), "r"(a[2]), "r"(a[3]), "r"(b[0]), "r"(b[1]));
}

#define XS 36

__global__ void __launch_bounds__(256) proj_kernel(
    const float* __restrict__ X,
    const float* __restrict__ Wh, const float* __restrict__ Wz,
    const float* __restrict__ bh, const float* __restrict__ bz,
    float* __restrict__ owh, float* __restrict__ owz)
{
    __shared__ float Xs[64*XS];
    __shared__ float Whs[64*XS];
    __shared__ float Wzs[64*XS];

    const int tid  = threadIdx.x;
    const int n0   = blockIdx.x * 64;
    const long m0  = (long)blockIdx.y * 64;
    const int lane = tid & 31;
    const int warp = tid >> 5;
    const int wm   = (warp & 3) * 16;
    const int wn   = (warp >> 2) * 32;
    const int gid  = lane >> 2;
    const int tig  = lane & 3;

    float ch[4][4], cz[4][4];
#pragma unroll
    for (int t = 0; t < 4; t++)
#pragma unroll
        for (int i = 0; i < 4; i++) { ch[t][i] = 0.f; cz[t][i] = 0.f; }

    for (int k0 = 0; k0 < 512; k0 += 32) {
        __syncthreads();
#pragma unroll
        for (int q = 0; q < 2; q++) {
            int idx = tid + 256*q;
            int row = idx >> 3;
            int col = (idx & 7) * 4;
            *(float4*)&Xs [row*XS + col] = *(const float4*)&X [(m0 + row)*512 + k0 + col];
            *(float4*)&Whs[row*XS + col] = *(const float4*)&Wh[(long)(n0 + row)*512 + k0 + col];
            *(float4*)&Wzs[row*XS + col] = *(const float4*)&Wz[(long)(n0 + row)*512 + k0 + col];
        }
        __syncthreads();

#pragma unroll
        for (int k8 = 0; k8 < 32; k8 += 8) {
            unsigned ahi[4], alo[4];
            {
                float v0 = Xs[(wm + gid    )*XS + k8 + tig    ];
                float v1 = Xs[(wm + gid + 8)*XS + k8 + tig    ];
                float v2 = Xs[(wm + gid    )*XS + k8 + tig + 4];
                float v3 = Xs[(wm + gid + 8)*XS + k8 + tig + 4];
                split_tf32(v0, ahi[0], alo[0]);
                split_tf32(v1, ahi[1], alo[1]);
                split_tf32(v2, ahi[2], alo[2]);
                split_tf32(v3, ahi[3], alo[3]);
            }
#pragma unroll
            for (int t = 0; t < 4; t++) {
                const int nn = wn + t*8 + gid;
                unsigned bhh[2], bhl[2], bzh[2], bzl[2];
                {
                    float w0 = Whs[nn*XS + k8 + tig    ];
                    float w1 = Whs[nn*XS + k8 + tig + 4];
                    split_tf32(w0, bhh[0], bhl[0]);
                    split_tf32(w1, bhh[1], bhl[1]);
                    float z0 = Wzs[nn*XS + k8 + tig    ];
                    float z1 = Wzs[nn*XS + k8 + tig + 4];
                    split_tf32(z0, bzh[0], bzl[0]);
                    split_tf32(z1, bzh[1], bzl[1]);
                }
                mma_tf32(ch[t], ahi, bhh);
                mma_tf32(ch[t], ahi, bhl);
                mma_tf32(ch[t], alo, bhh);
                mma_tf32(cz[t], ahi, bzh);
                mma_tf32(cz[t], ahi, bzl);
                mma_tf32(cz[t], alo, bzh);
            }
        }
    }

#pragma unroll
    for (int t = 0; t < 4; t++) {
        int colg = n0 + wn + t*8 + tig*2;
        float bh0 = bh[colg], bh1 = bh[colg + 1];
        float bz0 = bz[colg], bz1 = bz[colg + 1];
        long r0 = (m0 + wm + gid    )*512 + colg;
        long r1 = (m0 + wm + gid + 8)*512 + colg;
        owh[r0]     = ch[t][0] + bh0;
        owh[r0 + 1] = ch[t][1] + bh1;
        owh[r1]     = ch[t][2] + bh0;
        owh[r1 + 1] = ch[t][3] + bh1;
        owz[r0]     = cz[t][0] + bz0;
        owz[r0 + 1] = cz[t][1] + bz1;
        owz[r1]     = cz[t][2] + bz0;
        owz[r1 + 1] = cz[t][3] + bz1;
    }
}

// =====================================================================
// bf16 split helpers (scan) — round-8 proven
// =====================================================================
__device__ __forceinline__ unsigned pack_bf16(float lo_elem, float hi_elem) {
    unsigned w;
    asm("cvt.rn.bf16x2.f32 %0, %1, %2;" : "=r"(w) : "f"(hi_elem), "f"(lo_elem));
    return w;
}
__device__ __forceinline__ float bfw_lo(unsigned w) { return __uint_as_float(w << 16); }
__device__ __forceinline__ float bfw_hi(unsigned w) { return __uint_as_float(w & 0xFFFF0000u); }

__device__ __forceinline__ void mma_bf16(float* c, const unsigned* a, const unsigned* b) {
    asm volatile("mma.sync.aligned.m16n8k16.row.col.f32.bf16.bf16.f32 "
        "{%0,%1,%2,%3}, {%4,%5,%6,%7}, {%8,%9}, {%0,%1,%2,%3};"
        : "+f"(c[0]), "+f"(c[1]), "+f"(c[2]), "+f"(c[3])
        : "r"(a[0]), "r"(a[1]), "r"(a[2]), "r"(a[3]), "r"(b[0]), "r"(b[1]));
}

// =====================================================================
// Stage B: single-group persistent scan, 2 phases/step, n=8 MMA fully
// used. Grid: 128 CTAs = 8 groups (8 batches) x 16 H-slices (32 each).
// Sync primitives restored to round-8 proven forms:
//   poll   : ld.global.acquire.gpu
//   publish: __syncthreads(); tid0 { __threadfence(); atomicAdd; }
// =====================================================================
#define UPS 260
#define UPLANE (32*UPS)
#define BPLANE (8*UPS)
#define OFF_UZH 0
#define OFF_UZL (OFF_UZH + UPLANE)
#define OFF_UHH (OFF_UZL + UPLANE)
#define OFF_UHL (OFF_UHH + UPLANE)
#define OFF_BH  (OFF_UHL + UPLANE)
#define OFF_BL  (OFF_BH + BPLANE)
#define OFF_RED (OFF_BL + BPLANE)
#define SCAN_SMEM_WORDS (OFF_RED + 8*264)
#define SCAN_SMEM_BYTES (SCAN_SMEM_WORDS*4)

__device__ __forceinline__ void wait_flag(const unsigned int* f, unsigned tgt)
{
    unsigned v;
    do {
        asm volatile("ld.global.acquire.gpu.u32 %0, [%1];" : "=r"(v) : "l"(f));
    } while (v < tgt);
}

// stage 8 batches x warp's 64 j into packed bf16 hi/lo planes [b][k2]
__device__ __forceinline__ void stage_bf16(unsigned* __restrict__ Bh,
                                           unsigned* __restrict__ Bl,
                                           const float* __restrict__ src,
                                           int warp, int lane)
{
#pragma unroll
    for (int r = 0; r < 4; r++) {
        int q = lane + 32*r;            // 0..127
        int b = q >> 4;                 // 0..7
        int quad = q & 15;
        float4 v = __ldcg((const float4*)(src + b*512 + (warp << 6) + quad*4));
        unsigned h0 = pack_bf16(v.x, v.y);
        unsigned h1 = pack_bf16(v.z, v.w);
        unsigned l0 = pack_bf16(v.x - bfw_lo(h0), v.y - bfw_hi(h0));
        unsigned l1 = pack_bf16(v.z - bfw_lo(h1), v.w - bfw_hi(h1));
        int k2 = (warp << 5) + quad*2;
        *(uint2*)(Bh + b*UPS + k2) = make_uint2(h0, h1);
        *(uint2*)(Bl + b*UPS + k2) = make_uint2(l0, l1);
    }
    __syncwarp();
}

// warp GEMM partial over warp's k64: C[32i x 8b], 3-term split-bf16
__device__ __forceinline__ void gemm_mma(const unsigned* __restrict__ Bh,
                                         const unsigned* __restrict__ Bl,
                                         const unsigned* __restrict__ Uh,
                                         const unsigned* __restrict__ Ul,
                                         float* __restrict__ red,
                                         int warp, int lane)
{
    const int gid = lane >> 2;
    const int tig = lane & 3;

    float c0[4] = {0.f,0.f,0.f,0.f};
    float c1[4] = {0.f,0.f,0.f,0.f};

#pragma unroll
    for (int kc = 0; kc < 4; kc++) {
        const int k2 = (warp << 5) + (kc << 3) + tig;
        unsigned bhf[2], blf[2];
        bhf[0] = Bh[gid*UPS + k2];  bhf[1] = Bh[gid*UPS + k2 + 4];
        blf[0] = Bl[gid*UPS + k2];  blf[1] = Bl[gid*UPS + k2 + 4];

#pragma unroll
        for (int iw = 0; iw < 2; iw++) {
            const int r0 = iw*16 + gid;
            unsigned ah[4], al[4];
            ah[0] = Uh[(r0    )*UPS + k2    ];
            ah[1] = Uh[(r0 + 8)*UPS + k2    ];
            ah[2] = Uh[(r0    )*UPS + k2 + 4];
            ah[3] = Uh[(r0 + 8)*UPS + k2 + 4];
            al[0] = Ul[(r0    )*UPS + k2    ];
            al[1] = Ul[(r0 + 8)*UPS + k2    ];
            al[2] = Ul[(r0    )*UPS + k2 + 4];
            al[3] = Ul[(r0 + 8)*UPS + k2 + 4];
            float* cc = iw ? c1 : c0;
            mma_bf16(cc, ah, bhf);
            mma_bf16(cc, ah, blf);
            mma_bf16(cc, al, bhf);
        }
    }

    float* rp = red + warp*264;
#pragma unroll
    for (int iw = 0; iw < 2; iw++) {
        const float* cc = iw ? c1 : c0;
        int ia = iw*16 + gid;
        rp[(2*tig    )*33 + ia    ] = cc[0];
        rp[(2*tig + 1)*33 + ia    ] = cc[1];
        rp[(2*tig    )*33 + ia + 8] = cc[2];
        rp[(2*tig + 1)*33 + ia + 8] = cc[3];
    }
}

__global__ void __launch_bounds__(256) scan_kernel(
    const float* __restrict__ wh, const float* __restrict__ wz,
    const float* __restrict__ Uh, const float* __restrict__ Uz,
    float* __restrict__ out,
    float* __restrict__ hT, float* __restrict__ zhT,
    unsigned int* __restrict__ bar)
{
    extern __shared__ float sm[];
    unsigned* UZH = (unsigned*)(sm + OFF_UZH);
    unsigned* UZL = (unsigned*)(sm + OFF_UZL);
    unsigned* UHH = (unsigned*)(sm + OFF_UHH);
    unsigned* UHL = (unsigned*)(sm + OFF_UHL);
    unsigned* BH  = (unsigned*)(sm + OFF_BH);
    unsigned* BL  = (unsigned*)(sm + OFF_BL);
    float*    red = sm + OFF_RED;

    const int tid  = threadIdx.x;
    const int s    = blockIdx.x & 15;   // H slice
    const int g    = blockIdx.x >> 4;   // group 0..7
    const int i0   = s * 32;
    const int warp = tid >> 5;
    const int lane = tid & 31;

    // one-time U pre-split into packed bf16 hi/lo planes
    for (int idx = tid; idx < 32*256; idx += 256) {
        int i  = idx >> 8;
        int j2 = idx & 255;
        float2 uz = *(const float2*)&Uz[(i0 + i)*512 + 2*j2];
        unsigned h = pack_bf16(uz.x, uz.y);
        UZH[i*UPS + j2] = h;
        UZL[i*UPS + j2] = pack_bf16(uz.x - bfw_lo(h), uz.y - bfw_hi(h));
        float2 uh = *(const float2*)&Uh[(i0 + i)*512 + 2*j2];
        unsigned h2 = pack_bf16(uh.x, uh.y);
        UHH[i*UPS + j2] = h2;
        UHL[i*UPS + j2] = pack_bf16(uh.x - bfw_lo(h2), uh.y - bfw_hi(h2));
    }
    __syncthreads();

    // every thread owns one (b, i): bl = tid>>5, il = tid&31
    const int bl = tid >> 5;
    const int il = tid & 31;
    const int jg = i0 + il;

    float* hTg  = hT  + g*4096;
    float* zhTg = zhT + g*4096;
    unsigned int* barg = bar + g;

    float h_own = 0.f;

    for (int t = 0; t < T_; t++) {
        long base = ((long)(t*B_) + g*8 + bl)*(long)H_ + jg;
        float wzv = __ldcg(wz + base);
        float whv = __ldcg(wh + base);

        // ================= phase Z =================
        wait_flag(barg, 32u*(unsigned)t);
        stage_bf16(BH, BL, hTg, warp, lane);
        gemm_mma(BH, BL, UZH, UZL, red, warp, lane);
        __syncthreads();

        float sum = 0.f;
#pragma unroll
        for (int w = 0; w < 8; w++) sum += red[w*264 + bl*33 + il];
        float z  = __fdividef(1.f, 1.f + __expf(-(sum + wzv)));
        float zh = z * h_own;
        zhTg[bl*512 + jg] = zh;
        __syncthreads();
        if (tid == 0) { __threadfence(); atomicAdd(barg, 1u); }

        // ================= phase H =================
        wait_flag(barg, 32u*(unsigned)t + 16u);
        stage_bf16(BH, BL, zhTg, warp, lane);
        gemm_mma(BH, BL, UHH, UHL, red, warp, lane);
        __syncthreads();

        float sum2 = 0.f;
#pragma unroll
        for (int w = 0; w < 8; w++) sum2 += red[w*264 + bl*33 + il];
        float ahv = sum2 + whv;
        float hc = __fdividef(2.f, 1.f + __expf(-2.f*ahv)) - 1.f;
        float hn = zh + (1.f - z)*hc;
        h_own = hn;
        hTg[bl*512 + jg] = hn;
        out[base] = hn;
        __syncthreads();
        if (tid == 0) { __threadfence(); atomicAdd(barg, 1u); }
    }
}

// =====================================================================
extern "C" void kernel_launch(void* const* d_in, const int* in_sizes, int n_in,
                              void* d_out, int out_size)
{
    const float* x   = (const float*)d_in[0];
    const float* Wh0 = (const float*)d_in[1];
    const float* bh0 = (const float*)d_in[2];
    const float* Wz0 = (const float*)d_in[3];
    const float* bz0 = (const float*)d_in[4];
    const float* Uh0 = (const float*)d_in[5];
    const float* Uz0 = (const float*)d_in[6];
    const float* Wh1 = (const float*)d_in[7];
    const float* bh1 = (const float*)d_in[8];
    const float* Wz1 = (const float*)d_in[9];
    const float* bz1 = (const float*)d_in[10];
    const float* Uh1 = (const float*)d_in[11];
    const float* Uz1 = (const float*)d_in[12];
    float* out = (float*)d_out;

    float *p_wh, *p_wz, *p_h1, *p_hT, *p_zhT;
    unsigned int* p_bar;
    cudaGetSymbolAddress((void**)&p_wh, g_wh);
    cudaGetSymbolAddress((void**)&p_wz, g_wz);
    cudaGetSymbolAddress((void**)&p_h1, g_h1);
    cudaGetSymbolAddress((void**)&p_hT, g_hT);
    cudaGetSymbolAddress((void**)&p_zhT, g_zhT);
    cudaGetSymbolAddress((void**)&p_bar, g_bar);

    cudaFuncSetAttribute(scan_kernel,
                         cudaFuncAttributeMaxDynamicSharedMemorySize, SCAN_SMEM_BYTES);

    dim3 pgrid(8, 2000);

    // ---- Layer 0 ----
    proj_kernel<<<pgrid, 256>>>(x, Wh0, Wz0, bh0, bz0, p_wh, p_wz);
    cudaMemsetAsync(p_hT, 0, 8*8*512*sizeof(float));
    cudaMemsetAsync(p_bar, 0, 8*sizeof(unsigned int));
    scan_kernel<<<128, 256, SCAN_SMEM_BYTES>>>(p_wh, p_wz, Uh0, Uz0,
                                               p_h1, p_hT, p_zhT, p_bar);

    // ---- Layer 1 ----
    proj_kernel<<<pgrid, 256>>>(p_h1, Wh1, Wz1, bh1, bz1, p_wh, p_wz);
    cudaMemsetAsync(p_hT, 0, 8*8*512*sizeof(float));
    cudaMemsetAsync(p_bar, 0, 8*sizeof(unsigned int));
    scan_kernel<<<128, 256, SCAN_SMEM_BYTES>>>(p_wh, p_wz, Uh1, Uz1,
                                               out, p_hT, p_zhT, p_bar);
}

// round 11
// speedup vs baseline: 2.1133x; 1.0256x over previous
#include <cuda_runtime.h>
#include <math.h>

#define T_ 2000
#define B_ 64
#define H_ 512
#define TB_ (T_*B_)

// ---- scratch ----
__device__ float g_wh[TB_*H_];
__device__ float g_wz[TB_*H_];
__device__ float g_h1[TB_*H_];
__device__ float g_hT[8*8*512];      // [group][b][512 j]
__device__ float g_zhT[8*8*512];     // [group][b][512 j]
__device__ unsigned int g_bar[8];

// =====================================================================
// tf32 helpers
// =====================================================================
__device__ __forceinline__ unsigned cvt_tf32(float x) {
    unsigned r; asm("cvt.rna.tf32.f32 %0, %1;" : "=r"(r) : "f"(x)); return r;
}
__device__ __forceinline__ void split_tf32f(float x, float& hi, float& lo) {
    unsigned h = cvt_tf32(x);
    hi = __uint_as_float(h);
    lo = __uint_as_float(cvt_tf32(x - hi));
}
__device__ __forceinline__ void mma_tf32(float* c, const unsigned* a, const unsigned* b) {
    asm volatile("mma.sync.aligned.m16n8k8.row.col.f32.tf32.tf32.f32 "
        "{%0,%1,%2,%3}, {%4,%5,%6,%7}, {%8,%9}, {%0,%1,%2,%3};"
        : "+f"(c[0]), "+f"(c[1]), "+f"(c[2]), "+f"(c[3])
        : "r"(a[0]), "r"(a[1]), "r"(a[2]), "r"(a[3]), "r"(b[0]), "r"(b[1]));
}

// =====================================================================
// Stage A: fused dual projection, 3xTF32, PRE-SPLIT SMEM planes.
// Each element is cvt-split exactly ONCE at tile load; the k-inner
// loop is pure LDS + MMA. Dynamic SMEM: 6 planes x 64 x 36 = 55KB.
// Indexing is identical to the proven round-8 proj (same XS=36 layout).
// =====================================================================
#define XS 36
#define PROJ_SMEM_BYTES (6*64*XS*4)

__global__ void __launch_bounds__(256) proj_kernel(
    const float* __restrict__ X,
    const float* __restrict__ Wh, const float* __restrict__ Wz,
    const float* __restrict__ bh, const float* __restrict__ bz,
    float* __restrict__ owh, float* __restrict__ owz)
{
    extern __shared__ float ps[];
    float* Xh  = ps;
    float* Xl  = ps + 64*XS;
    float* Whh = ps + 2*64*XS;
    float* Whl = ps + 3*64*XS;
    float* Wzh = ps + 4*64*XS;
    float* Wzl = ps + 5*64*XS;

    const int tid  = threadIdx.x;
    const int n0   = blockIdx.x * 64;
    const long m0  = (long)blockIdx.y * 64;
    const int lane = tid & 31;
    const int warp = tid >> 5;
    const int wm   = (warp & 3) * 16;
    const int wn   = (warp >> 2) * 32;
    const int gid  = lane >> 2;
    const int tig  = lane & 3;

    float ch[4][4], cz[4][4];
#pragma unroll
    for (int t = 0; t < 4; t++)
#pragma unroll
        for (int i = 0; i < 4; i++) { ch[t][i] = 0.f; cz[t][i] = 0.f; }

    for (int k0 = 0; k0 < 512; k0 += 32) {
        __syncthreads();
#pragma unroll
        for (int q = 0; q < 2; q++) {
            int idx = tid + 256*q;
            int row = idx >> 3;
            int col = (idx & 7) * 4;
            float4 xa = *(const float4*)&X [(m0 + row)*512 + k0 + col];
            float4 wa = *(const float4*)&Wh[(long)(n0 + row)*512 + k0 + col];
            float4 za = *(const float4*)&Wz[(long)(n0 + row)*512 + k0 + col];
            float h0,l0,h1,l1,h2,l2,h3,l3;
            split_tf32f(xa.x,h0,l0); split_tf32f(xa.y,h1,l1);
            split_tf32f(xa.z,h2,l2); split_tf32f(xa.w,h3,l3);
            *(float4*)&Xh[row*XS + col] = make_float4(h0,h1,h2,h3);
            *(float4*)&Xl[row*XS + col] = make_float4(l0,l1,l2,l3);
            split_tf32f(wa.x,h0,l0); split_tf32f(wa.y,h1,l1);
            split_tf32f(wa.z,h2,l2); split_tf32f(wa.w,h3,l3);
            *(float4*)&Whh[row*XS + col] = make_float4(h0,h1,h2,h3);
            *(float4*)&Whl[row*XS + col] = make_float4(l0,l1,l2,l3);
            split_tf32f(za.x,h0,l0); split_tf32f(za.y,h1,l1);
            split_tf32f(za.z,h2,l2); split_tf32f(za.w,h3,l3);
            *(float4*)&Wzh[row*XS + col] = make_float4(h0,h1,h2,h3);
            *(float4*)&Wzl[row*XS + col] = make_float4(l0,l1,l2,l3);
        }
        __syncthreads();

#pragma unroll
        for (int k8 = 0; k8 < 32; k8 += 8) {
            unsigned ahi[4], alo[4];
            {
                int r0 = (wm + gid)*XS + k8 + tig;
                int r1 = (wm + gid + 8)*XS + k8 + tig;
                ahi[0] = __float_as_uint(Xh[r0    ]);
                ahi[1] = __float_as_uint(Xh[r1    ]);
                ahi[2] = __float_as_uint(Xh[r0 + 4]);
                ahi[3] = __float_as_uint(Xh[r1 + 4]);
                alo[0] = __float_as_uint(Xl[r0    ]);
                alo[1] = __float_as_uint(Xl[r1    ]);
                alo[2] = __float_as_uint(Xl[r0 + 4]);
                alo[3] = __float_as_uint(Xl[r1 + 4]);
            }
#pragma unroll
            for (int t = 0; t < 4; t++) {
                const int nn = (wn + t*8 + gid)*XS + k8 + tig;
                unsigned bhh[2], bhl[2], bzh[2], bzl[2];
                bhh[0] = __float_as_uint(Whh[nn]); bhh[1] = __float_as_uint(Whh[nn + 4]);
                bhl[0] = __float_as_uint(Whl[nn]); bhl[1] = __float_as_uint(Whl[nn + 4]);
                bzh[0] = __float_as_uint(Wzh[nn]); bzh[1] = __float_as_uint(Wzh[nn + 4]);
                bzl[0] = __float_as_uint(Wzl[nn]); bzl[1] = __float_as_uint(Wzl[nn + 4]);
                mma_tf32(ch[t], ahi, bhh);
                mma_tf32(ch[t], ahi, bhl);
                mma_tf32(ch[t], alo, bhh);
                mma_tf32(cz[t], ahi, bzh);
                mma_tf32(cz[t], ahi, bzl);
                mma_tf32(cz[t], alo, bzh);
            }
        }
    }

#pragma unroll
    for (int t = 0; t < 4; t++) {
        int colg = n0 + wn + t*8 + tig*2;
        float bh0 = bh[colg], bh1 = bh[colg + 1];
        float bz0 = bz[colg], bz1 = bz[colg + 1];
        long r0 = (m0 + wm + gid    )*512 + colg;
        long r1 = (m0 + wm + gid + 8)*512 + colg;
        owh[r0]     = ch[t][0] + bh0;
        owh[r0 + 1] = ch[t][1] + bh1;
        owh[r1]     = ch[t][2] + bh0;
        owh[r1 + 1] = ch[t][3] + bh1;
        owz[r0]     = cz[t][0] + bz0;
        owz[r0 + 1] = cz[t][1] + bz1;
        owz[r1]     = cz[t][2] + bz0;
        owz[r1 + 1] = cz[t][3] + bz1;
    }
}

// =====================================================================
// bf16 split helpers (scan) — round-10 proven, VERBATIM
// =====================================================================
__device__ __forceinline__ unsigned pack_bf16(float lo_elem, float hi_elem) {
    unsigned w;
    asm("cvt.rn.bf16x2.f32 %0, %1, %2;" : "=r"(w) : "f"(hi_elem), "f"(lo_elem));
    return w;
}
__device__ __forceinline__ float bfw_lo(unsigned w) { return __uint_as_float(w << 16); }
__device__ __forceinline__ float bfw_hi(unsigned w) { return __uint_as_float(w & 0xFFFF0000u); }

__device__ __forceinline__ void mma_bf16(float* c, const unsigned* a, const unsigned* b) {
    asm volatile("mma.sync.aligned.m16n8k16.row.col.f32.bf16.bf16.f32 "
        "{%0,%1,%2,%3}, {%4,%5,%6,%7}, {%8,%9}, {%0,%1,%2,%3};"
        : "+f"(c[0]), "+f"(c[1]), "+f"(c[2]), "+f"(c[3])
        : "r"(a[0]), "r"(a[1]), "r"(a[2]), "r"(a[3]), "r"(b[0]), "r"(b[1]));
}

// =====================================================================
// Stage B: single-group persistent scan, 2 phases/step — round-10
// proven version, VERBATIM.
// =====================================================================
#define UPS 260
#define UPLANE (32*UPS)
#define BPLANE (8*UPS)
#define OFF_UZH 0
#define OFF_UZL (OFF_UZH + UPLANE)
#define OFF_UHH (OFF_UZL + UPLANE)
#define OFF_UHL (OFF_UHH + UPLANE)
#define OFF_BH  (OFF_UHL + UPLANE)
#define OFF_BL  (OFF_BH + BPLANE)
#define OFF_RED (OFF_BL + BPLANE)
#define SCAN_SMEM_WORDS (OFF_RED + 8*264)
#define SCAN_SMEM_BYTES (SCAN_SMEM_WORDS*4)

__device__ __forceinline__ void wait_flag(const unsigned int* f, unsigned tgt)
{
    unsigned v;
    do {
        asm volatile("ld.global.acquire.gpu.u32 %0, [%1];" : "=r"(v) : "l"(f));
    } while (v < tgt);
}

__device__ __forceinline__ void stage_bf16(unsigned* __restrict__ Bh,
                                           unsigned* __restrict__ Bl,
                                           const float* __restrict__ src,
                                           int warp, int lane)
{
#pragma unroll
    for (int r = 0; r < 4; r++) {
        int q = lane + 32*r;            // 0..127
        int b = q >> 4;                 // 0..7
        int quad = q & 15;
        float4 v = __ldcg((const float4*)(src + b*512 + (warp << 6) + quad*4));
        unsigned h0 = pack_bf16(v.x, v.y);
        unsigned h1 = pack_bf16(v.z, v.w);
        unsigned l0 = pack_bf16(v.x - bfw_lo(h0), v.y - bfw_hi(h0));
        unsigned l1 = pack_bf16(v.z - bfw_lo(h1), v.w - bfw_hi(h1));
        int k2 = (warp << 5) + quad*2;
        *(uint2*)(Bh + b*UPS + k2) = make_uint2(h0, h1);
        *(uint2*)(Bl + b*UPS + k2) = make_uint2(l0, l1);
    }
    __syncwarp();
}

__device__ __forceinline__ void gemm_mma(const unsigned* __restrict__ Bh,
                                         const unsigned* __restrict__ Bl,
                                         const unsigned* __restrict__ Uh,
                                         const unsigned* __restrict__ Ul,
                                         float* __restrict__ red,
                                         int warp, int lane)
{
    const int gid = lane >> 2;
    const int tig = lane & 3;

    float c0[4] = {0.f,0.f,0.f,0.f};
    float c1[4] = {0.f,0.f,0.f,0.f};

#pragma unroll
    for (int kc = 0; kc < 4; kc++) {
        const int k2 = (warp << 5) + (kc << 3) + tig;
        unsigned bhf[2], blf[2];
        bhf[0] = Bh[gid*UPS + k2];  bhf[1] = Bh[gid*UPS + k2 + 4];
        blf[0] = Bl[gid*UPS + k2];  blf[1] = Bl[gid*UPS + k2 + 4];

#pragma unroll
        for (int iw = 0; iw < 2; iw++) {
            const int r0 = iw*16 + gid;
            unsigned ah[4], al[4];
            ah[0] = Uh[(r0    )*UPS + k2    ];
            ah[1] = Uh[(r0 + 8)*UPS + k2    ];
            ah[2] = Uh[(r0    )*UPS + k2 + 4];
            ah[3] = Uh[(r0 + 8)*UPS + k2 + 4];
            al[0] = Ul[(r0    )*UPS + k2    ];
            al[1] = Ul[(r0 + 8)*UPS + k2    ];
            al[2] = Ul[(r0    )*UPS + k2 + 4];
            al[3] = Ul[(r0 + 8)*UPS + k2 + 4];
            float* cc = iw ? c1 : c0;
            mma_bf16(cc, ah, bhf);
            mma_bf16(cc, ah, blf);
            mma_bf16(cc, al, bhf);
        }
    }

    float* rp = red + warp*264;
#pragma unroll
    for (int iw = 0; iw < 2; iw++) {
        const float* cc = iw ? c1 : c0;
        int ia = iw*16 + gid;
        rp[(2*tig    )*33 + ia    ] = cc[0];
        rp[(2*tig + 1)*33 + ia    ] = cc[1];
        rp[(2*tig    )*33 + ia + 8] = cc[2];
        rp[(2*tig + 1)*33 + ia + 8] = cc[3];
    }
}

__global__ void __launch_bounds__(256) scan_kernel(
    const float* __restrict__ wh, const float* __restrict__ wz,
    const float* __restrict__ Uh, const float* __restrict__ Uz,
    float* __restrict__ out,
    float* __restrict__ hT, float* __restrict__ zhT,
    unsigned int* __restrict__ bar)
{
    extern __shared__ float sm[];
    unsigned* UZH = (unsigned*)(sm + OFF_UZH);
    unsigned* UZL = (unsigned*)(sm + OFF_UZL);
    unsigned* UHH = (unsigned*)(sm + OFF_UHH);
    unsigned* UHL = (unsigned*)(sm + OFF_UHL);
    unsigned* BH  = (unsigned*)(sm + OFF_BH);
    unsigned* BL  = (unsigned*)(sm + OFF_BL);
    float*    red = sm + OFF_RED;

    const int tid  = threadIdx.x;
    const int s    = blockIdx.x & 15;   // H slice
    const int g    = blockIdx.x >> 4;   // group 0..7
    const int i0   = s * 32;
    const int warp = tid >> 5;
    const int lane = tid & 31;

    for (int idx = tid; idx < 32*256; idx += 256) {
        int i  = idx >> 8;
        int j2 = idx & 255;
        float2 uz = *(const float2*)&Uz[(i0 + i)*512 + 2*j2];
        unsigned h = pack_bf16(uz.x, uz.y);
        UZH[i*UPS + j2] = h;
        UZL[i*UPS + j2] = pack_bf16(uz.x - bfw_lo(h), uz.y - bfw_hi(h));
        float2 uh = *(const float2*)&Uh[(i0 + i)*512 + 2*j2];
        unsigned h2 = pack_bf16(uh.x, uh.y);
        UHH[i*UPS + j2] = h2;
        UHL[i*UPS + j2] = pack_bf16(uh.x - bfw_lo(h2), uh.y - bfw_hi(h2));
    }
    __syncthreads();

    const int bl = tid >> 5;
    const int il = tid & 31;
    const int jg = i0 + il;

    float* hTg  = hT  + g*4096;
    float* zhTg = zhT + g*4096;
    unsigned int* barg = bar + g;

    float h_own = 0.f;

    for (int t = 0; t < T_; t++) {
        long base = ((long)(t*B_) + g*8 + bl)*(long)H_ + jg;
        float wzv = __ldcg(wz + base);
        float whv = __ldcg(wh + base);

        // ================= phase Z =================
        wait_flag(barg, 32u*(unsigned)t);
        stage_bf16(BH, BL, hTg, warp, lane);
        gemm_mma(BH, BL, UZH, UZL, red, warp, lane);
        __syncthreads();

        float sum = 0.f;
#pragma unroll
        for (int w = 0; w < 8; w++) sum += red[w*264 + bl*33 + il];
        float z  = __fdividef(1.f, 1.f + __expf(-(sum + wzv)));
        float zh = z * h_own;
        zhTg[bl*512 + jg] = zh;
        __syncthreads();
        if (tid == 0) { __threadfence(); atomicAdd(barg, 1u); }

        // ================= phase H =================
        wait_flag(barg, 32u*(unsigned)t + 16u);
        stage_bf16(BH, BL, zhTg, warp, lane);
        gemm_mma(BH, BL, UHH, UHL, red, warp, lane);
        __syncthreads();

        float sum2 = 0.f;
#pragma unroll
        for (int w = 0; w < 8; w++) sum2 += red[w*264 + bl*33 + il];
        float ahv = sum2 + whv;
        float hc = __fdividef(2.f, 1.f + __expf(-2.f*ahv)) - 1.f;
        float hn = zh + (1.f - z)*hc;
        h_own = hn;
        hTg[bl*512 + jg] = hn;
        out[base] = hn;
        __syncthreads();
        if (tid == 0) { __threadfence(); atomicAdd(barg, 1u); }
    }
}

// =====================================================================
extern "C" void kernel_launch(void* const* d_in, const int* in_sizes, int n_in,
                              void* d_out, int out_size)
{
    const float* x   = (const float*)d_in[0];
    const float* Wh0 = (const float*)d_in[1];
    const float* bh0 = (const float*)d_in[2];
    const float* Wz0 = (const float*)d_in[3];
    const float* bz0 = (const float*)d_in[4];
    const float* Uh0 = (const float*)d_in[5];
    const float* Uz0 = (const float*)d_in[6];
    const float* Wh1 = (const float*)d_in[7];
    const float* bh1 = (const float*)d_in[8];
    const float* Wz1 = (const float*)d_in[9];
    const float* bz1 = (const float*)d_in[10];
    const float* Uh1 = (const float*)d_in[11];
    const float* Uz1 = (const float*)d_in[12];
    float* out = (float*)d_out;

    float *p_wh, *p_wz, *p_h1, *p_hT, *p_zhT;
    unsigned int* p_bar;
    cudaGetSymbolAddress((void**)&p_wh, g_wh);
    cudaGetSymbolAddress((void**)&p_wz, g_wz);
    cudaGetSymbolAddress((void**)&p_h1, g_h1);
    cudaGetSymbolAddress((void**)&p_hT, g_hT);
    cudaGetSymbolAddress((void**)&p_zhT, g_zhT);
    cudaGetSymbolAddress((void**)&p_bar, g_bar);

    cudaFuncSetAttribute(proj_kernel,
                         cudaFuncAttributeMaxDynamicSharedMemorySize, PROJ_SMEM_BYTES);
    cudaFuncSetAttribute(scan_kernel,
                         cudaFuncAttributeMaxDynamicSharedMemorySize, SCAN_SMEM_BYTES);

    dim3 pgrid(8, 2000);

    // ---- Layer 0 ----
    proj_kernel<<<pgrid, 256, PROJ_SMEM_BYTES>>>(x, Wh0, Wz0, bh0, bz0, p_wh, p_wz);
    cudaMemsetAsync(p_hT, 0, 8*8*512*sizeof(float));
    cudaMemsetAsync(p_bar, 0, 8*sizeof(unsigned int));
    scan_kernel<<<128, 256, SCAN_SMEM_BYTES>>>(p_wh, p_wz, Uh0, Uz0,
                                               p_h1, p_hT, p_zhT, p_bar);

    // ---- Layer 1 ----
    proj_kernel<<<pgrid, 256, PROJ_SMEM_BYTES>>>(p_h1, Wh1, Wz1, bh1, bz1, p_wh, p_wz);
    cudaMemsetAsync(p_hT, 0, 8*8*512*sizeof(float));
    cudaMemsetAsync(p_bar, 0, 8*sizeof(unsigned int));
    scan_kernel<<<128, 256, SCAN_SMEM_BYTES>>>(p_wh, p_wz, Uh1, Uz1,
                                               out, p_hT, p_zhT, p_bar);
}